// round 15
// baseline (speedup 1.0000x reference)
#include <cuda_runtime.h>
#include <cstdint>

#define BATCH 4
#define SEQ   2048
#define INF   4096
#define OUTF  4096
#define RANK  16
// SCALING = 16/16 = 1.0f (elided)

// ---- phase-1 ----
#define P1_SPLIT  8
#define KS_TOT    256                   // 16-wide k-steps total
#define KS_SPLIT  (KS_TOT / P1_SPLIT)   // 32 ks per split (512 k)
#define P1_CK     64                    // k per staged chunk
#define P1_NCHK   8
#define XPITCH    72                    // bf16 elems per smem row (144 B)

#define NOT       (OUTF / 8)            // 512 o-tiles
#define NRT       (BATCH * SEQ / 16)    // 512 row-tiles

// scratch
__device__ float    g_bx[P1_SPLIT * BATCH * SEQ * RANK];   // 4 MB partials
__device__ uint32_t g_Bc[8 * 2 * KS_TOT * 128];            // 2 MB packed B
__device__ uint32_t g_Af[8 * NOT * 128];                   // 2 MB packed A
__device__ uint32_t g_bxf[NRT * 256];                      // 512 KB packed Bx

// ---- helpers --------------------------------------------------------------
__device__ __forceinline__ uint32_t bfhi2(float f0, float f1) {
    return __byte_perm(__float_as_uint(f0), __float_as_uint(f1), 0x7632);
}
__device__ __forceinline__ uint32_t bflo2(float f0, float f1) {
    const float l0 = f0 - __uint_as_float(__float_as_uint(f0) & 0xFFFF0000u);
    const float l1 = f1 - __uint_as_float(__float_as_uint(f1) & 0xFFFF0000u);
    return __byte_perm(__float_as_uint(l0), __float_as_uint(l1), 0x7632);
}
__device__ __forceinline__ void mma16816(float* d,
    uint32_t a0, uint32_t a1, uint32_t a2, uint32_t a3,
    uint32_t b0, uint32_t b1)
{
    asm volatile(
        "mma.sync.aligned.m16n8k16.row.col.f32.bf16.bf16.f32 "
        "{%0,%1,%2,%3}, {%4,%5,%6,%7}, {%8,%9}, {%0,%1,%2,%3};"
        : "+f"(d[0]), "+f"(d[1]), "+f"(d[2]), "+f"(d[3])
        : "r"(a0), "r"(a1), "r"(a2), "r"(a3), "r"(b0), "r"(b1));
}
__device__ __forceinline__ void ldmx4(uint32_t& r0, uint32_t& r1,
                                      uint32_t& r2, uint32_t& r3, uint32_t addr)
{
    asm volatile("ldmatrix.sync.aligned.m8n8.x4.shared.b16 {%0,%1,%2,%3}, [%4];"
                 : "=r"(r0), "=r"(r1), "=r"(r2), "=r"(r3) : "r"(addr));
}
__device__ __forceinline__ uint32_t smem_u32(const void* p) {
    return (uint32_t)__cvta_generic_to_shared(p);
}

// ---------------------------------------------------------------------------
// K0: merged conv (B-frags then A-frags). [validated R13/R14]
// ---------------------------------------------------------------------------
#define NBW (8 * KS_TOT * 2 * 2 * 32)    // 262144 B-threads
__global__ void lora_conv(const float* __restrict__ Bw,
                          const float* __restrict__ Aw)
{
    const int gidx = blockIdx.x * blockDim.x + threadIdx.x;
    if (gidx < NBW) {
        const int lane = gidx & 31;
        const int t    = (gidx >> 5) & 1;
        const int j    = (gidx >> 6) & 1;
        const int ks   = (gidx >> 7) & (KS_TOT - 1);
        const int a    = gidx >> 15;
        const int r    = t * 8 + (lane >> 2);
        const float2 f = *(const float2*)(Bw + ((size_t)a * RANK + r) * INF
                                          + ks * 16 + j * 8 + (lane & 3) * 2);
        const uint32_t off = (uint32_t)(((ks * 2 + j) * 2 + t) * 32 + lane);
        g_Bc[(uint32_t)(a * 2 + 0) * (KS_TOT * 128) + off] = bfhi2(f.x, f.y);
        g_Bc[(uint32_t)(a * 2 + 1) * (KS_TOT * 128) + off] = bflo2(f.x, f.y);
    } else {
        const int idx  = gidx - NBW;
        const int lane = idx & 31;
        const int j    = (idx >> 5) & 1;
        const int ot   = (idx >> 6) & (NOT - 1);
        const int a    = idx >> 15;
        const int o    = ot * 8 + (lane >> 2);
        const float2 f = *(const float2*)(Aw + ((size_t)a * OUTF + o) * RANK
                                          + j * 8 + (lane & 3) * 2);
        uint32_t* dst = g_Af + (uint32_t)(a * NOT + ot) * 128u;
        dst[j * 32 + lane]      = bfhi2(f.x, f.y);
        dst[64 + j * 32 + lane] = bflo2(f.x, f.y);
    }
}

// ---------------------------------------------------------------------------
// K1: phase-1 MMA, coalesced x staging + ldmatrix, double-buffered planes,
// ONE barrier per chunk.
// ---------------------------------------------------------------------------
__global__ __launch_bounds__(128) void lora_p1_mma(
    const float* __restrict__ x,
    const int*   __restrict__ ids)
{
    __shared__ __align__(16) uint16_t sh0[64 * XPITCH];
    __shared__ __align__(16) uint16_t sh1[64 * XPITCH];
    __shared__ __align__(16) uint16_t sl0[64 * XPITCH];
    __shared__ __align__(16) uint16_t sl1[64 * XPITCH];

    const int tid  = threadIdx.x;
    const int wid  = tid >> 5;
    const int lane = tid & 31;
    const int b    = blockIdx.y;
    const int sp   = blockIdx.z;
    const int aid  = ids[b];
    const int rowBase = blockIdx.x * 64;

    const float* xb = x + ((size_t)b * SEQ + rowBase) * INF + sp * (KS_SPLIT * 16);
    const uint32_t* Bhi = g_Bc + (size_t)(aid * 2 + 0) * (KS_TOT * 128);
    const uint32_t* Blo = g_Bc + (size_t)(aid * 2 + 1) * (KS_TOT * 128);

    uint16_t* const shp[2] = {sh0, sh1};
    uint16_t* const slp[2] = {sl0, sl1};
    const uint32_t shb[2] = {smem_u32(sh0), smem_u32(sh1)};
    const uint32_t slb[2] = {smem_u32(sl0), smem_u32(sl1)};
    const uint32_t lmoff = (uint32_t)(wid * 16 + (lane & 15)) * 144u
                         + (uint32_t)(lane >> 4) * 16u;

    float c0h[4] = {0,0,0,0}, c0m[4] = {0,0,0,0}, c0l[4] = {0,0,0,0};
    float c1h[4] = {0,0,0,0}, c1m[4] = {0,0,0,0}, c1l[4] = {0,0,0,0};

    float4 xr[8];
#pragma unroll
    for (int i = 0; i < 8; ++i) {
        const int idx = i * 128 + tid, row = idx >> 4, c4 = idx & 15;
        xr[i] = *(const float4*)(xb + (size_t)row * INF + c4 * 4);
    }

#pragma unroll 1
    for (int ch = 0; ch < P1_NCHK; ++ch) {
        const int st = ch & 1;
        uint16_t* sh = shp[st];
        uint16_t* sl = slp[st];
        // STS staged chunk (f32 -> bf16 hi/lo); buffer st was consumed in ch-2
#pragma unroll
        for (int i = 0; i < 8; ++i) {
            const int idx = i * 128 + tid, row = idx >> 4, c4 = idx & 15;
            const uint32_t off = (uint32_t)row * XPITCH + (uint32_t)c4 * 4;
            *(uint32_t*)(sh + off)     = bfhi2(xr[i].x, xr[i].y);
            *(uint32_t*)(sh + off + 2) = bfhi2(xr[i].z, xr[i].w);
            *(uint32_t*)(sl + off)     = bflo2(xr[i].x, xr[i].y);
            *(uint32_t*)(sl + off + 2) = bflo2(xr[i].z, xr[i].w);
        }
        __syncthreads();
        if (ch + 1 < P1_NCHK) {
#pragma unroll
            for (int i = 0; i < 8; ++i) {
                const int idx = i * 128 + tid, row = idx >> 4, c4 = idx & 15;
                xr[i] = *(const float4*)(xb + (size_t)row * INF
                                         + (ch + 1) * P1_CK + c4 * 4);
            }
        }
#pragma unroll
        for (int ksi = 0; ksi < 4; ++ksi) {
            uint32_t ah0, ah1, ah2, ah3, al0, al1, al2, al3;
            ldmx4(ah0, ah1, ah2, ah3, shb[st] + lmoff + ksi * 32);
            ldmx4(al0, al1, al2, al3, slb[st] + lmoff + ksi * 32);
            const int ksg = sp * KS_SPLIT + ch * 4 + ksi;
            const uint32_t* bp = Bhi + ksg * 128 + lane;
            const uint32_t* lp = Blo + ksg * 128 + lane;
            const uint32_t bh00 = bp[0],  bh01 = bp[64];
            const uint32_t bh10 = bp[32], bh11 = bp[96];
            const uint32_t bl00 = lp[0],  bl01 = lp[64];
            const uint32_t bl10 = lp[32], bl11 = lp[96];

            mma16816(c0h, ah0, ah1, ah2, ah3, bh00, bh01);
            mma16816(c1h, ah0, ah1, ah2, ah3, bh10, bh11);
            mma16816(c0m, al0, al1, al2, al3, bh00, bh01);
            mma16816(c1m, al0, al1, al2, al3, bh10, bh11);
            mma16816(c0l, ah0, ah1, ah2, ah3, bl00, bl01);
            mma16816(c1l, ah0, ah1, ah2, ah3, bl10, bl11);
        }
    }

    float acc0[4], acc1[4];
#pragma unroll
    for (int i = 0; i < 4; ++i) {
        acc0[i] = c0h[i] + c0m[i] + c0l[i];
        acc1[i] = c1h[i] + c1m[i] + c1l[i];
    }

    const int row0 = rowBase + wid * 16 + (lane >> 2);
    const int tig  = lane & 3;
    float* d0 = g_bx + ((size_t)(sp * BATCH + b) * SEQ + row0) * RANK;
    float* d8 = d0 + 8 * RANK;
    *(float2*)(d0 + tig * 2)     = make_float2(acc0[0], acc0[1]);
    *(float2*)(d8 + tig * 2)     = make_float2(acc0[2], acc0[3]);
    *(float2*)(d0 + 8 + tig * 2) = make_float2(acc1[0], acc1[1]);
    *(float2*)(d8 + 8 + tig * 2) = make_float2(acc1[2], acc1[3]);
}

// ---------------------------------------------------------------------------
// K1b: reduce 8 partials -> packed Bx a-frags (R10-validated layout).
// Thread idx = rt*128 + q*32 + lane; q: bit0 = row+8, bit1 = k+8.
// ---------------------------------------------------------------------------
__global__ __launch_bounds__(256) void lora_reduce()
{
    const int idx  = blockIdx.x * 256 + threadIdx.x;   // 0..65535
    const int lane = idx & 31;
    const int q    = (idx >> 5) & 3;
    const int rt   = idx >> 7;
    const int b    = rt >> 7;
    const int n    = (rt & 127) * 16 + (lane >> 2) + (q & 1) * 8;
    const int k0   = (lane & 3) * 2 + (q >> 1) * 8;

    float2 s = {0.f, 0.f};
#pragma unroll
    for (int sp = 0; sp < P1_SPLIT; ++sp) {
        const float2 v = *(const float2*)(g_bx +
            ((size_t)(sp * BATCH + b) * SEQ + n) * RANK + k0);
        s.x += v.x; s.y += v.y;
    }
    uint32_t* dst = g_bxf + (uint32_t)rt * 256u + (uint32_t)q * 32u + lane;
    dst[0]   = bfhi2(s.x, s.y);
    dst[128] = bflo2(s.x, s.y);
}

// ---------------------------------------------------------------------------
// K2: phase-2 MMA. A-frags in CTA smem, Bx a-frags from g_bxf (pre-reduced),
// 2 row-tiles/warp with hoisted A loads, smem-staged coalesced stores.
// ---------------------------------------------------------------------------
#define P2_SMEM (32768 + 2 * 34816)    // A chunk + double store buffer
__global__ __launch_bounds__(256) void lora_p2_mma(
    const int* __restrict__ ids,
    float*     __restrict__ out)
{
    extern __shared__ __align__(16) char p2sm[];
    uint32_t* Asm = (uint32_t*)p2sm;                   // 8192 words
    float*    buf = (float*)(p2sm + 32768);            // [8 warps][2][16][68]

    const int tid  = threadIdx.x;
    const int wid  = tid >> 5;
    const int lane = tid & 31;
    const int oc   = blockIdx.x;                       // 0..7
    const int g    = blockIdx.y;                       // 0..31
    const int rt0  = g * 16 + wid * 2;
    const int b    = rt0 >> 7;
    const int aid  = ids[b];

    // stage A chunk (coalesced)
    {
        const uint4* src = (const uint4*)(g_Af + (size_t)aid * (NOT * 128) + oc * 8192);
        uint4* dst = (uint4*)Asm;
#pragma unroll
        for (int i = 0; i < 8; ++i) dst[i * 256 + tid] = src[i * 256 + tid];
    }
    __syncthreads();

    // load pre-reduced Bx a-frags for both row-tiles (coalesced LDG.32)
    uint32_t ah[2][4], al[2][4];
#pragma unroll
    for (int r = 0; r < 2; ++r) {
        const uint32_t* f = g_bxf + (uint32_t)(rt0 + r) * 256u + lane;
#pragma unroll
        for (int i = 0; i < 4; ++i) {
            ah[r][i] = f[i * 32];
            al[r][i] = f[128 + i * 32];
        }
    }

    float* outb0 = out + ((size_t)b * SEQ + (rt0 & 127) * 16) * OUTF;
    float* b0 = buf + wid * (2 * 16 * 68);
    float* b1 = b0 + 16 * 68;
    const int r4 = lane >> 2;
    const int co = (lane & 3) * 2;

#pragma unroll 1
    for (int c8 = 0; c8 < 8; ++c8) {
        const int colb = oc * 512 + c8 * 64;
#pragma unroll
        for (int oti = 0; oti < 8; ++oti) {
            const uint32_t* ap = Asm + (c8 * 8 + oti) * 128 + lane;
            const uint32_t bh0 = ap[0],  bh1 = ap[32];
            const uint32_t bl0 = ap[64], bl1 = ap[96];
            float c0[4] = {0.f, 0.f, 0.f, 0.f};
            float c1[4] = {0.f, 0.f, 0.f, 0.f};
            mma16816(c0, ah[0][0], ah[0][1], ah[0][2], ah[0][3], bh0, bh1);
            mma16816(c0, al[0][0], al[0][1], al[0][2], al[0][3], bh0, bh1);
            mma16816(c0, ah[0][0], ah[0][1], ah[0][2], ah[0][3], bl0, bl1);
            mma16816(c1, ah[1][0], ah[1][1], ah[1][2], ah[1][3], bh0, bh1);
            mma16816(c1, al[1][0], al[1][1], al[1][2], al[1][3], bh0, bh1);
            mma16816(c1, ah[1][0], ah[1][1], ah[1][2], ah[1][3], bl0, bl1);
            *(float2*)&b0[r4 * 68 + oti * 8 + co]       = make_float2(c0[0], c0[1]);
            *(float2*)&b0[(r4 + 8) * 68 + oti * 8 + co] = make_float2(c0[2], c0[3]);
            *(float2*)&b1[r4 * 68 + oti * 8 + co]       = make_float2(c1[0], c1[1]);
            *(float2*)&b1[(r4 + 8) * 68 + oti * 8 + co] = make_float2(c1[2], c1[3]);
        }
        __syncwarp();
#pragma unroll
        for (int r = 0; r < 2; ++r) {
            float* ob = outb0 + (size_t)r * 16 * OUTF;
            const float* bb = r ? b1 : b0;
#pragma unroll
            for (int i = 0; i < 8; ++i) {
                const int row = i * 2 + (lane >> 4);
                const int f4  = lane & 15;
                *(float4*)(ob + (size_t)row * OUTF + colb + f4 * 4) =
                    *(const float4*)&bb[row * 68 + f4 * 4];
            }
        }
        __syncwarp();
    }
}

// ---------------------------------------------------------------------------
extern "C" void kernel_launch(void* const* d_in, const int* in_sizes, int n_in,
                              void* d_out, int out_size)
{
    const float* x   = (const float*)d_in[0];   // [4,2048,4096]
    const float* Aw  = (const float*)d_in[1];   // [8,4096,16]
    const float* Bw  = (const float*)d_in[2];   // [8,16,4096]
    const int*   ids = (const int*)  d_in[3];   // [4]
    float*       out = (float*)d_out;           // [4,2048,4096]

    cudaFuncSetAttribute(lora_p2_mma,
                         cudaFuncAttributeMaxDynamicSharedMemorySize, P2_SMEM);

    lora_conv<<<(2 * NBW) / 256, 256>>>(Bw, Aw);          // 2048 CTAs

    dim3 g1(SEQ / 64, BATCH, P1_SPLIT);                   // (32,4,8) = 1024 CTAs
    lora_p1_mma<<<g1, 128>>>(x, ids);

    lora_reduce<<<256, 256>>>();                          // 256 CTAs

    dim3 g2(8, 32);                                       // 256 CTAs
    lora_p2_mma<<<g2, 256, P2_SMEM>>>(ids, out);
}